// round 13
// baseline (speedup 1.0000x reference)
#include <cuda_runtime.h>
#include <cuda_bf16.h>
#include <math.h>
#include <stdint.h>

// Problem constants
#define B_ 128
#define T_ 512
#define I_ 256
#define H_ 1024
#define O_ 256

#define NB   128      // persistent grid: 4 M-tiles x 32 N-tiles
#define NTHR 256      // 8 warps: warps 0-3 = stream 0 (even chunks), 4-7 = stream 1 (odd)

// ---------------------------------------------------------------------------
// Device-global scratch (allocation-free per harness rules)
// ---------------------------------------------------------------------------
__device__ __nv_bfloat16 g_x_hi[(size_t)B_ * T_ * I_];
__device__ __nv_bfloat16 g_x_lo[(size_t)B_ * T_ * I_];
__device__ __nv_bfloat16 g_wih_hi[H_ * I_];
__device__ __nv_bfloat16 g_wih_lo[H_ * I_];
__device__ float g_xp[(size_t)B_ * T_ * H_];     // x @ W_ih^T (no bias), fp32
__device__ __nv_bfloat16 g_h_hi[2][B_ * H_];
__device__ __nv_bfloat16 g_h_lo[2][B_ * H_];
__device__ float g_h32[B_ * H_];
// Group-local barriers: batch-group g uses slot g*32 (128B padding)
__device__ unsigned g_bar_count4[128];
__device__ unsigned g_bar_phase4[128];

// ---------------------------------------------------------------------------
// Recurrence SMEM layout: W_hh hi/lo + 3 stages per stream
// ---------------------------------------------------------------------------
#define SM_WHH_HI 0                      // 64KB (32 rows x 2048B, col^row swizzle)
#define SM_WHH_LO 65536                  // 64KB
#define SM_ASTAGE 131072                 // 2 streams x 3 stages x 16384 = 96KB
#define SM_RED    (131072 + 49152)       // alias: stream1 stage 0 (safe post-compute)
#define SM_BIAS   229376                 // 32 floats
#define SM_TOTAL  229504

// xp GEMM SMEM layout (separate kernel): A 64x512B hi/lo, B 128x512B hi/lo
#define XP_A_HI 0
#define XP_A_LO 32768
#define XP_B_HI 65536
#define XP_B_LO 131072
#define XP_SMEM 196608

// ---------------------------------------------------------------------------
// PTX helpers (portable ISA for plain sm_103 target — NO tcgen05)
// ---------------------------------------------------------------------------
__device__ __forceinline__ uint32_t smem_u32(const void* p) {
    uint32_t a;
    asm("{ .reg .u64 t; cvta.to.shared.u64 t, %1; cvt.u32.u64 %0, t; }" : "=r"(a) : "l"(p));
    return a;
}

__device__ __forceinline__ void cp16(uint32_t saddr, const void* gptr) {
    asm volatile("cp.async.cg.shared.global [%0], [%1], 16;"
                 :: "r"(saddr), "l"(__cvta_generic_to_global(gptr)));
}

__device__ __forceinline__ void ldsm_x4(uint32_t* r, uint32_t addr) {
    asm volatile("ldmatrix.sync.aligned.m8n8.x4.shared.b16 {%0,%1,%2,%3}, [%4];"
                 : "=r"(r[0]), "=r"(r[1]), "=r"(r[2]), "=r"(r[3]) : "r"(addr));
}

__device__ __forceinline__ void mma16816(float* c, const uint32_t* a, uint32_t b0, uint32_t b1) {
    asm volatile(
        "mma.sync.aligned.m16n8k16.row.col.f32.bf16.bf16.f32 "
        "{%0,%1,%2,%3}, {%4,%5,%6,%7}, {%8,%9}, {%0,%1,%2,%3};"
        : "+f"(c[0]), "+f"(c[1]), "+f"(c[2]), "+f"(c[3])
        : "r"(a[0]), "r"(a[1]), "r"(a[2]), "r"(a[3]), "r"(b0), "r"(b1));
}

__device__ __forceinline__ void stream_bar(int stream) {
    asm volatile("bar.sync %0, 128;" :: "r"(1 + stream) : "memory");
}

// Group-local sense-reversing barrier: 32 CTAs sharing a batch group (ctaM)
__device__ __forceinline__ void group_barrier(int grp, unsigned* phase) {
    __syncthreads();
    if (threadIdx.x == 0) {
        unsigned target = *phase + 1;
        unsigned* cnt = &g_bar_count4[grp * 32];
        unsigned* ph  = &g_bar_phase4[grp * 32];
        if (atomicAdd(cnt, 1) == 31) {
            *cnt = 0;
            __threadfence();
            atomicExch(ph, target);
        } else {
            while (((volatile unsigned*)ph)[0] != target) {}
            __threadfence();
        }
        *phase = target;
    }
    __syncthreads();
}

// ---------------------------------------------------------------------------
// Split prep kernel
// ---------------------------------------------------------------------------
__global__ void split_pair(const float* __restrict__ src,
                           __nv_bfloat16* __restrict__ hi,
                           __nv_bfloat16* __restrict__ lo, int n)
{
    int i = blockIdx.x * blockDim.x + threadIdx.x;
    if (i < n) {
        float v = src[i];
        __nv_bfloat16 h = __float2bfloat16(v);
        hi[i] = h;
        lo[i] = __float2bfloat16(v - __bfloat162float(h));
    }
}

// ---------------------------------------------------------------------------
// xp GEMM: xp[bt][n] = sum_i x[bt][i] * W_ih[n][i]   (split-bf16 3-term)
// CTA tile 64(bt) x 128(n), K=256 fully resident. Grid (1024, 8), 256 thr.
// 8 warps as 2x4: warp tile M32 x N32.
// ---------------------------------------------------------------------------
__global__ __launch_bounds__(256) void xp_gemm()
{
    extern __shared__ char sm[];
    const uint32_t smb = smem_u32(sm);
    const int tid = threadIdx.x;
    const int lid = tid & 31;
    const int wid = tid >> 5;
    const int wm = wid >> 2, wn = wid & 3;
    const int m0 = blockIdx.x * 64;       // bt row tile
    const int n0 = blockIdx.y * 128;      // output col tile

    // Load A (x) 64 rows x 512B hi/lo and B (W_ih) 128 rows x 512B hi/lo.
    // Swizzle: (col16B) ^ ((row&7)*16), rows 512B — same as proven W_ih path.
    {
        const char* xhi = (const char*)g_x_hi;
        const char* xlo = (const char*)g_x_lo;
        #pragma unroll
        for (int i = 0; i < 8; i++) {
            int u = tid + i * 256;
            int row = u >> 5, uk = u & 31;
            int so = row * 512 + ((uk * 16) ^ ((row & 7) * 16));
            size_t go = (size_t)(m0 + row) * 512 + uk * 16;
            cp16(smb + XP_A_HI + so, xhi + go);
            cp16(smb + XP_A_LO + so, xlo + go);
        }
        const char* whi = (const char*)g_wih_hi;
        const char* wlo = (const char*)g_wih_lo;
        #pragma unroll
        for (int i = 0; i < 16; i++) {
            int u = tid + i * 256;
            int row = u >> 5, uk = u & 31;
            int so = row * 512 + ((uk * 16) ^ ((row & 7) * 16));
            size_t go = (size_t)(n0 + row) * 512 + uk * 16;
            cp16(smb + XP_B_HI + so, whi + go);
            cp16(smb + XP_B_LO + so, wlo + go);
        }
    }
    asm volatile("cp.async.commit_group;");
    asm volatile("cp.async.wait_group 0;");
    __syncthreads();

    const int arow = (lid & 7) + ((lid >> 3) & 1) * 8;
    const int aka2 = ((lid >> 4) & 1) * 16;
    const int axor = (arow & 7) * 16;
    const int bro  = (lid & 7) + ((lid >> 4) & 1) * 8;
    const int bka2 = ((lid >> 3) & 1) * 16;

    float acc[2][2][2][2][4];   // parity, mb, nb, cfrag, 4
    #pragma unroll
    for (int p = 0; p < 2; p++)
        #pragma unroll
        for (int a = 0; a < 2; a++)
            #pragma unroll
            for (int b = 0; b < 2; b++)
                #pragma unroll
                for (int cfr = 0; cfr < 2; cfr++)
                    #pragma unroll
                    for (int j = 0; j < 4; j++) acc[p][a][b][cfr][j] = 0.f;

    #pragma unroll
    for (int kk = 0; kk < 16; kk++) {
        uint32_t ahi[2][4], alo[2][4], bh[2][4], bl[2][4];
        #pragma unroll
        for (int mb = 0; mb < 2; mb++) {
            uint32_t aaddr = smb + XP_A_HI +
                (uint32_t)(wm * 32 + mb * 16 + arow) * 512 +
                (uint32_t)((kk * 32 + aka2) ^ axor);
            ldsm_x4(ahi[mb], aaddr);
            ldsm_x4(alo[mb], aaddr + 32768);
        }
        #pragma unroll
        for (int nb = 0; nb < 2; nb++) {
            int brow = wn * 32 + nb * 16 + bro;
            uint32_t baddr = smb + XP_B_HI + (uint32_t)brow * 512 +
                (uint32_t)((kk * 32 + bka2) ^ ((brow & 7) * 16));
            ldsm_x4(bh[nb], baddr);
            ldsm_x4(bl[nb], baddr + 65536);
        }
        const int p = kk & 1;
        #pragma unroll
        for (int mb = 0; mb < 2; mb++)
            #pragma unroll
            for (int nb = 0; nb < 2; nb++) {
                float* C0 = acc[p][mb][nb][0];
                float* C1 = acc[p][mb][nb][1];
                mma16816(C0, ahi[mb], bh[nb][0], bh[nb][1]);
                mma16816(C1, ahi[mb], bh[nb][2], bh[nb][3]);
                mma16816(C0, ahi[mb], bl[nb][0], bl[nb][1]);
                mma16816(C1, ahi[mb], bl[nb][2], bl[nb][3]);
                mma16816(C0, alo[mb], bh[nb][0], bh[nb][1]);
                mma16816(C1, alo[mb], bh[nb][2], bh[nb][3]);
            }
    }

    const int g  = lid >> 2;
    const int tg = lid & 3;
    #pragma unroll
    for (int mb = 0; mb < 2; mb++)
        #pragma unroll
        for (int nb = 0; nb < 2; nb++)
            #pragma unroll
            for (int cfr = 0; cfr < 2; cfr++)
                #pragma unroll
                for (int rp = 0; rp < 2; rp++) {
                    int row = m0 + wm * 32 + mb * 16 + g + rp * 8;
                    int col = n0 + wn * 32 + nb * 16 + cfr * 8 + tg * 2;
                    float2 v;
                    v.x = acc[0][mb][nb][cfr][rp * 2 + 0] + acc[1][mb][nb][cfr][rp * 2 + 0];
                    v.y = acc[0][mb][nb][cfr][rp * 2 + 1] + acc[1][mb][nb][cfr][rp * 2 + 1];
                    *(float2*)(g_xp + (size_t)row * H_ + col) = v;
                }
}

// ---------------------------------------------------------------------------
// Recurrence chunk loader: 128 threads load 16KB (hi 8KB + lo 8KB) of h.
// Chunk c in 0..7 = K cols c*128..c*128+127.
// ---------------------------------------------------------------------------
__device__ __forceinline__ void load_chunk(uint32_t sstage, int c,
    const char* __restrict__ hhi, const char* __restrict__ hlo,
    int m0, int stid)
{
    #pragma unroll
    for (int i = 0; i < 4; i++) {
        int u = stid + i * 128;
        int row = u >> 4, uk = u & 15;
        int so = row * 256 + ((uk * 16) ^ ((row & 7) * 16));
        size_t go = (size_t)(m0 + row) * 2048 + (size_t)c * 256 + uk * 16;
        cp16(sstage + so, hhi + go);
        cp16(sstage + 8192 + so, hlo + go);
    }
}

// ---------------------------------------------------------------------------
// Persistent recurrence: 512 steps. K = 1024 (h only; x folded via g_xp).
// Dual K-parity streams of 4 warps (M16xN16), 3 stages/stream, distance-2
// prefetch; group-local barriers.
// ---------------------------------------------------------------------------
__global__ __launch_bounds__(NTHR, 1) void rnn_persistent(
    const float* __restrict__ b_ih, const float* __restrict__ b_hh,
    const float* __restrict__ Whh)
{
    extern __shared__ char sm[];
    const uint32_t smb = smem_u32(sm);
    const int tid = threadIdx.x;
    const int lid = tid & 31;
    const int wid = tid >> 5;
    const int stream = wid >> 2;
    const int stid = tid & 127;
    const int swid = wid & 3;
    const int wm = swid >> 1, wn = swid & 1;
    const int ctaM = blockIdx.x >> 5;
    const int ctaN = blockIdx.x & 31;
    const int m0 = ctaM * 32;
    const int n0 = ctaN * 32;

    // ---- Prologue: split W_hh slice fp32 -> bf16 hi/lo into smem ----
    {
        for (int u = tid; u < 8192; u += NTHR) {
            int row = u >> 8, k4 = u & 255;
            float4 v = *(const float4*)(Whh + (size_t)(n0 + row) * H_ + k4 * 4);
            __nv_bfloat162 h01 = __floats2bfloat162_rn(v.x, v.y);
            __nv_bfloat162 h23 = __floats2bfloat162_rn(v.z, v.w);
            __nv_bfloat162 l01 = __floats2bfloat162_rn(
                v.x - __bfloat162float(h01.x), v.y - __bfloat162float(h01.y));
            __nv_bfloat162 l23 = __floats2bfloat162_rn(
                v.z - __bfloat162float(h23.x), v.w - __bfloat162float(h23.y));
            int so = row * 2048 + ((k4 * 8) ^ ((row & 7) * 16));
            uint2 hp; hp.x = *(uint32_t*)&h01; hp.y = *(uint32_t*)&h23;
            uint2 lp; lp.x = *(uint32_t*)&l01; lp.y = *(uint32_t*)&l23;
            *(uint2*)(sm + SM_WHH_HI + so) = hp;
            *(uint2*)(sm + SM_WHH_LO + so) = lp;
        }
        if (tid < 32)
            ((float*)(sm + SM_BIAS))[tid] = b_ih[n0 + tid] + b_hh[n0 + tid];
    }

    unsigned phase = 0;
    if (tid == 0) phase = ((volatile unsigned*)&g_bar_phase4[ctaM * 32])[0];
    __syncthreads();

    const int arow = (lid & 7) + ((lid >> 3) & 1) * 8;
    const int aka2 = ((lid >> 4) & 1) * 16;
    const int axor = (arow & 7) * 16;
    const uint32_t stage_base = smb + SM_ASTAGE + (uint32_t)stream * 49152;
    const uint32_t a_lane = stage_base + (uint32_t)(wm * 16 + arow) * 256;

    const int brow = wn * 16 + (lid & 7) + ((lid >> 4) & 1) * 8;
    const int bka2 = ((lid >> 3) & 1) * 16;
    const int bxor = (brow & 7) * 16;
    const uint32_t bhh_lane = smb + SM_WHH_HI + (uint32_t)brow * 2048;

    const int g  = lid >> 2;
    const int tg = lid & 3;

    for (int t = 0; t < T_; t++) {
        const char* hhi = (const char*)g_h_hi[t & 1];
        const char* hlo = (const char*)g_h_lo[t & 1];

        // Stream 0 prefetches its xp values for this step (consumed in epilogue)
        float2 xpv[2][2];
        if (stream == 0) {
            #pragma unroll
            for (int nt = 0; nt < 2; nt++)
                #pragma unroll
                for (int rp = 0; rp < 2; rp++) {
                    int mg = m0 + wm * 16 + g + rp * 8;
                    int ng = n0 + wn * 16 + nt * 8 + tg * 2;
                    xpv[nt][rp] = __ldg((const float2*)
                        (g_xp + ((size_t)mg * T_ + t) * H_ + ng));
                }
        }

        float acc[2][2][4];
        #pragma unroll
        for (int p = 0; p < 2; p++)
            #pragma unroll
            for (int n = 0; n < 2; n++)
                #pragma unroll
                for (int j = 0; j < 4; j++) acc[p][n][j] = 0.f;

        // Stream s: chunks {s, s+2, s+4, s+6}; 3 stages, distance-2 prefetch.
        load_chunk(stage_base,         stream,     hhi, hlo, m0, stid);
        asm volatile("cp.async.commit_group;");
        load_chunk(stage_base + 16384, stream + 2, hhi, hlo, m0, stid);
        asm volatile("cp.async.commit_group;");

        #pragma unroll
        for (int i = 0; i < 4; i++) {
            if (i < 3) asm volatile("cp.async.wait_group 1;");
            else       asm volatile("cp.async.wait_group 0;");
            stream_bar(stream);   // chunk i visible; all warps done with chunk i-1
            const int c = 2 * i + stream;
            if (i < 2) {          // prefetch chunk i+2 into stage (i+2)%3
                load_chunk(stage_base + (uint32_t)(((i + 2) % 3)) * 16384,
                           c + 4, hhi, hlo, m0, stid);
                asm volatile("cp.async.commit_group;");
            }

            const uint32_t a_base = a_lane + (uint32_t)(i % 3) * 16384;
            const int kb0 = c * 256;

            #pragma unroll
            for (int kk = 0; kk < 8; kk++) {
                uint32_t ahi[4], alo[4], bh[4], bl[4];
                uint32_t ao = (uint32_t)((kk * 32 + aka2) ^ axor);
                ldsm_x4(ahi, a_base + ao);
                ldsm_x4(alo, a_base + 8192 + ao);
                uint32_t bo = (uint32_t)((kb0 + kk * 32 + bka2) ^ bxor);
                ldsm_x4(bh, bhh_lane + bo);        // NON-trans: [n][k] row-major
                ldsm_x4(bl, bhh_lane + 65536 + bo);

                float* C0 = acc[kk & 1][0];
                float* C1 = acc[kk & 1][1];
                mma16816(C0, ahi, bh[0], bh[1]);   // Ahi*Bhi
                mma16816(C1, ahi, bh[2], bh[3]);
                mma16816(C0, ahi, bl[0], bl[1]);   // Ahi*Blo
                mma16816(C1, ahi, bl[2], bl[3]);
                mma16816(C0, alo, bh[0], bh[1]);   // Alo*Bhi
                mma16816(C1, alo, bh[2], bh[3]);
            }
        }
        stream_bar(stream);   // all stream warps done before red-buffer reuse

        // ---- Epilogue: merge streams, +xp +bias, tanh, split-bf16 store ----
        {
            float vs[2][4];
            #pragma unroll
            for (int nt = 0; nt < 2; nt++)
                #pragma unroll
                for (int j = 0; j < 4; j++)
                    vs[nt][j] = acc[0][nt][j] + acc[1][nt][j];

            float* red = (float*)(sm + SM_RED);   // stream1 stage 0 (idle now)
            if (stream == 1) {
                #pragma unroll
                for (int nt = 0; nt < 2; nt++) {
                    int nloc = wn * 16 + nt * 8 + tg * 2;
                    #pragma unroll
                    for (int rp = 0; rp < 2; rp++) {
                        int mloc = wm * 16 + g + rp * 8;
                        red[mloc * 32 + nloc]     = vs[nt][rp * 2 + 0];
                        red[mloc * 32 + nloc + 1] = vs[nt][rp * 2 + 1];
                    }
                }
            }
            __syncthreads();
            if (stream == 0) {
                __nv_bfloat16* __restrict__ ohi = g_h_hi[(t + 1) & 1];
                __nv_bfloat16* __restrict__ olo = g_h_lo[(t + 1) & 1];
                const float* bias = (const float*)(sm + SM_BIAS);
                const bool last = (t == T_ - 1);
                #pragma unroll
                for (int nt = 0; nt < 2; nt++) {
                    int nloc = wn * 16 + nt * 8 + tg * 2;
                    int ng = n0 + nloc;
                    float b0v = bias[nloc], b1v = bias[nloc + 1];
                    #pragma unroll
                    for (int rp = 0; rp < 2; rp++) {
                        int mloc = wm * 16 + g + rp * 8;
                        int mg = m0 + mloc;
                        float v0 = tanhf(vs[nt][rp * 2 + 0] + red[mloc * 32 + nloc]
                                         + b0v + xpv[nt][rp].x);
                        float v1 = tanhf(vs[nt][rp * 2 + 1] + red[mloc * 32 + nloc + 1]
                                         + b1v + xpv[nt][rp].y);
                        __nv_bfloat16 h0 = __float2bfloat16(v0);
                        __nv_bfloat16 h1 = __float2bfloat16(v1);
                        __nv_bfloat16 l0 = __float2bfloat16(v0 - __bfloat162float(h0));
                        __nv_bfloat16 l1 = __float2bfloat16(v1 - __bfloat162float(h1));
                        size_t idx = (size_t)mg * H_ + ng;
                        *(uint32_t*)(ohi + idx) =
                            ((uint32_t)*(uint16_t*)&h1 << 16) | *(uint16_t*)&h0;
                        *(uint32_t*)(olo + idx) =
                            ((uint32_t)*(uint16_t*)&l1 << 16) | *(uint16_t*)&l0;
                        if (last) {
                            float2 f2v; f2v.x = v0; f2v.y = v1;
                            *(float2*)(g_h32 + idx) = f2v;
                        }
                    }
                }
            }
        }

        __threadfence();   // h stores visible GPU-wide before barrier release
        group_barrier(ctaM, &phase);
    }
}

// ---------------------------------------------------------------------------
// fc epilogue: one block per batch; warp-per-output-column, lanes split K.
// ---------------------------------------------------------------------------
__global__ __launch_bounds__(256) void fc_kernel(
    const float* __restrict__ W_fc, const float* __restrict__ b_fc,
    float* __restrict__ out)
{
    __shared__ float4 hsv4[H_ / 4];
    const int b = blockIdx.x;
    const int tid = threadIdx.x;
    const int wid = tid >> 5;
    const int lid = tid & 31;

    hsv4[tid] = ((const float4*)(g_h32 + (size_t)b * H_))[tid];
    __syncthreads();

    #pragma unroll 4
    for (int oi = 0; oi < 32; oi++) {
        const int o = wid * 32 + oi;
        const float4* __restrict__ w4 = (const float4*)(W_fc + (size_t)o * H_);
        float a0 = 0.f, a1 = 0.f;
        #pragma unroll
        for (int i = 0; i < 8; i++) {
            float4 w = w4[lid + i * 32];
            float4 h = hsv4[lid + i * 32];
            if (i & 1) a1 += w.x * h.x + w.y * h.y + w.z * h.z + w.w * h.w;
            else       a0 += w.x * h.x + w.y * h.y + w.z * h.z + w.w * h.w;
        }
        float acc = a0 + a1;
        #pragma unroll
        for (int off = 16; off > 0; off >>= 1)
            acc += __shfl_xor_sync(0xFFFFFFFFu, acc, off);
        if (lid == 0) out[(size_t)b * O_ + o] = acc + b_fc[o];
    }
}

__global__ void copy_hidden(float* __restrict__ dst)
{
    int idx = blockIdx.x * blockDim.x + threadIdx.x;
    if (idx < B_ * H_) dst[idx] = g_h32[idx];
}

// ---------------------------------------------------------------------------
extern "C" void kernel_launch(void* const* d_in, const int* in_sizes, int n_in,
                              void* d_out, int out_size)
{
    const float* x      = (const float*)d_in[0];
    const float* hidden = (const float*)d_in[1];
    const float* W_ih   = (const float*)d_in[2];
    const float* W_hh   = (const float*)d_in[3];
    const float* b_ih   = (const float*)d_in[4];
    const float* b_hh   = (const float*)d_in[5];
    const float* W_fc   = (const float*)d_in[6];
    const float* b_fc   = (const float*)d_in[7];
    float* out = (float*)d_out;

    cudaFuncSetAttribute(rnn_persistent, cudaFuncAttributeMaxDynamicSharedMemorySize,
                         SM_TOTAL);
    cudaFuncSetAttribute(xp_gemm, cudaFuncAttributeMaxDynamicSharedMemorySize,
                         XP_SMEM);

    static __nv_bfloat16 *p_xhi = nullptr, *p_xlo = nullptr,
                         *p_whi = nullptr, *p_wlo = nullptr,
                         *p_hhi = nullptr, *p_hlo = nullptr;
    if (!p_xhi) {
        cudaGetSymbolAddress((void**)&p_xhi, g_x_hi);
        cudaGetSymbolAddress((void**)&p_xlo, g_x_lo);
        cudaGetSymbolAddress((void**)&p_whi, g_wih_hi);
        cudaGetSymbolAddress((void**)&p_wlo, g_wih_lo);
        cudaGetSymbolAddress((void**)&p_hhi, g_h_hi);
        cudaGetSymbolAddress((void**)&p_hlo, g_h_lo);
    }

    // 1) split x, W_ih, initial hidden to bf16 hi/lo
    split_pair<<<(B_ * T_ * I_ + 255) / 256, 256>>>(x, p_xhi, p_xlo, B_ * T_ * I_);
    split_pair<<<(H_ * I_ + 255) / 256, 256>>>(W_ih, p_whi, p_wlo, H_ * I_);
    split_pair<<<(B_ * H_ + 255) / 256, 256>>>(hidden, p_hhi, p_hlo, B_ * H_);

    // 2) one-shot input projection (fully parallel tensor-core GEMM)
    xp_gemm<<<dim3((B_ * T_) / 64, H_ / 128), 256, XP_SMEM>>>();

    // 3) full recurrence in ONE persistent launch (K = 1024, 8 chunks)
    rnn_persistent<<<NB, NTHR, SM_TOTAL>>>(b_ih, b_hh, W_hh);

    // 4) fc epilogue + hidden output
    fc_kernel<<<B_, 256>>>(W_fc, b_fc, out);
    if (out_size >= B_ * O_ + B_ * H_)
        copy_hidden<<<(B_ * H_ + 255) / 256, 256>>>(out + B_ * O_);
}

// round 14
// speedup vs baseline: 1.0122x; 1.0122x over previous
#include <cuda_runtime.h>
#include <cuda_bf16.h>
#include <math.h>
#include <stdint.h>

// Problem constants
#define B_ 128
#define T_ 512
#define I_ 256
#define H_ 1024
#define O_ 256

#define NB   128      // persistent grid: 4 M-tiles x 32 N-tiles
#define NTHR 256      // 8 warps: warps 0-3 = stream 0, warps 4-7 = stream 1

// ---------------------------------------------------------------------------
// Device-global scratch (allocation-free per harness rules)
// ---------------------------------------------------------------------------
__device__ __nv_bfloat16 g_x_hi[(size_t)B_ * T_ * I_];
__device__ __nv_bfloat16 g_x_lo[(size_t)B_ * T_ * I_];
__device__ __nv_bfloat16 g_h_hi[2][B_ * H_];
__device__ __nv_bfloat16 g_h_lo[2][B_ * H_];
__device__ float g_h32[B_ * H_];
// Group-local barriers: batch-group g uses slot g*32 (128B padding)
__device__ unsigned g_bar_count4[128];
__device__ unsigned g_bar_phase4[128];

// ---------------------------------------------------------------------------
// SMEM layout (identical footprint to the proven 3267us version)
// ---------------------------------------------------------------------------
#define SM_WHH_HI 0            // 32 rows x 2048B, swizzled (col XOR row)
#define SM_WHH_LO 65536
#define SM_WIH_HI 131072       // 32 rows x 512B, swizzled (col XOR row)
#define SM_WIH_LO 147456
#define SM_ASTAGE 163840       // stream0: 2 stages x 16K; stream1 at +32768
#define SM_BIAS   229376       // 32 floats
#define SM_TOTAL  229632
// red buffer: aliases stream0's stage (t&1) — free during the epilogue
// (chunk j=4 compute done before the post-loop __syncthreads; next write to
//  that stage happens after the NEXT group barrier).

// ---------------------------------------------------------------------------
// PTX helpers (portable ISA for plain sm_103 target — NO tcgen05)
// ---------------------------------------------------------------------------
__device__ __forceinline__ uint32_t smem_u32(const void* p) {
    uint32_t a;
    asm("{ .reg .u64 t; cvta.to.shared.u64 t, %1; cvt.u32.u64 %0, t; }" : "=r"(a) : "l"(p));
    return a;
}

__device__ __forceinline__ void cp16(uint32_t saddr, const void* gptr) {
    asm volatile("cp.async.cg.shared.global [%0], [%1], 16;"
                 :: "r"(saddr), "l"(__cvta_generic_to_global(gptr)));
}

__device__ __forceinline__ void ldsm_x4(uint32_t* r, uint32_t addr) {
    asm volatile("ldmatrix.sync.aligned.m8n8.x4.shared.b16 {%0,%1,%2,%3}, [%4];"
                 : "=r"(r[0]), "=r"(r[1]), "=r"(r[2]), "=r"(r[3]) : "r"(addr));
}

__device__ __forceinline__ void mma16816(float* c, const uint32_t* a, uint32_t b0, uint32_t b1) {
    asm volatile(
        "mma.sync.aligned.m16n8k16.row.col.f32.bf16.bf16.f32 "
        "{%0,%1,%2,%3}, {%4,%5,%6,%7}, {%8,%9}, {%0,%1,%2,%3};"
        : "+f"(c[0]), "+f"(c[1]), "+f"(c[2]), "+f"(c[3])
        : "r"(a[0]), "r"(a[1]), "r"(a[2]), "r"(a[3]), "r"(b0), "r"(b1));
}

__device__ __forceinline__ void stream_bar(int stream) {
    asm volatile("bar.sync %0, 128;" :: "r"(1 + stream) : "memory");
}

// Group-local sense-reversing barrier: 32 CTAs sharing a batch group (ctaM)
__device__ __forceinline__ void group_barrier(int grp, unsigned* phase) {
    __syncthreads();
    if (threadIdx.x == 0) {
        unsigned target = *phase + 1;
        unsigned* cnt = &g_bar_count4[grp * 32];
        unsigned* ph  = &g_bar_phase4[grp * 32];
        if (atomicAdd(cnt, 1) == 31) {
            *cnt = 0;
            __threadfence();
            atomicExch(ph, target);
        } else {
            while (((volatile unsigned*)ph)[0] != target) {}
            __threadfence();
        }
        *phase = target;
    }
    __syncthreads();
}

// ---------------------------------------------------------------------------
// Split prep kernel (x and initial hidden; W splits happen in prologue)
// ---------------------------------------------------------------------------
__global__ void split_pair(const float* __restrict__ src,
                           __nv_bfloat16* __restrict__ hi,
                           __nv_bfloat16* __restrict__ lo, int n)
{
    int i = blockIdx.x * blockDim.x + threadIdx.x;
    if (i < n) {
        float v = src[i];
        __nv_bfloat16 h = __float2bfloat16(v);
        hi[i] = h;
        lo[i] = __float2bfloat16(v - __bfloat162float(h));
    }
}

// ---------------------------------------------------------------------------
// Stream-local chunk loader: 128 threads load 16KB (hi 8KB + lo 8KB).
// Swizzle: column offset XOR ((row&7)*16). c<8: h slice; c>=8: x_t slice.
// ---------------------------------------------------------------------------
__device__ __forceinline__ void load_chunk(uint32_t sstage, int c,
    const char* __restrict__ hhi, const char* __restrict__ hlo,
    int m0, int t, int stid)
{
    if (c < 8) {
        #pragma unroll
        for (int i = 0; i < 4; i++) {
            int u = stid + i * 128;
            int row = u >> 4, uk = u & 15;
            int so = row * 256 + ((uk * 16) ^ ((row & 7) * 16));
            size_t go = (size_t)(m0 + row) * 2048 + (size_t)c * 256 + uk * 16;
            cp16(sstage + so, hhi + go);
            cp16(sstage + 8192 + so, hlo + go);
        }
    } else {
        int cx = c - 8;
        #pragma unroll
        for (int i = 0; i < 4; i++) {
            int u = stid + i * 128;
            int row = u >> 4, uk = u & 15;
            int so = row * 256 + ((uk * 16) ^ ((row & 7) * 16));
            size_t go = ((size_t)(m0 + row) * T_ + t) * 512 + (size_t)cx * 256 + uk * 16;
            cp16(sstage + so, (const char*)g_x_hi + go);
            cp16(sstage + 8192 + so, (const char*)g_x_lo + go);
        }
    }
}

// ---------------------------------------------------------------------------
// Persistent recurrence: 512 steps, one launch.
// Stream s chunks per step: {x(8+s), h(0+s), h(2+s), h(4+s), h(6+s)}.
// x chunk of step t+1 is PRE-STAGED during step t (x doesn't depend on h),
// so the only barrier-dependent load (h chunk 0) is covered by x-compute.
// Epilogue split by n-subtile across streams.
// ---------------------------------------------------------------------------
__global__ __launch_bounds__(NTHR, 1) void rnn_persistent(
    const float* __restrict__ b_ih, const float* __restrict__ b_hh,
    const float* __restrict__ Whh, const float* __restrict__ Wih)
{
    extern __shared__ char sm[];
    const uint32_t smb = smem_u32(sm);
    const int tid = threadIdx.x;
    const int lid = tid & 31;
    const int wid = tid >> 5;
    const int stream = wid >> 2;
    const int stid = tid & 127;
    const int swid = wid & 3;
    const int wm = swid >> 1, wn = swid & 1;
    const int ctaM = blockIdx.x >> 5;
    const int ctaN = blockIdx.x & 31;
    const int m0 = ctaM * 32;
    const int n0 = ctaN * 32;

    // ---- Prologue: split W slices fp32 -> bf16 hi/lo directly into smem ----
    {
        for (int u = tid; u < 8192; u += NTHR) {
            int row = u >> 8, k4 = u & 255;
            float4 v = *(const float4*)(Whh + (size_t)(n0 + row) * H_ + k4 * 4);
            __nv_bfloat162 h01 = __floats2bfloat162_rn(v.x, v.y);
            __nv_bfloat162 h23 = __floats2bfloat162_rn(v.z, v.w);
            __nv_bfloat162 l01 = __floats2bfloat162_rn(
                v.x - __bfloat162float(h01.x), v.y - __bfloat162float(h01.y));
            __nv_bfloat162 l23 = __floats2bfloat162_rn(
                v.z - __bfloat162float(h23.x), v.w - __bfloat162float(h23.y));
            int so = row * 2048 + ((k4 * 8) ^ ((row & 7) * 16));
            uint2 hp; hp.x = *(uint32_t*)&h01; hp.y = *(uint32_t*)&h23;
            uint2 lp; lp.x = *(uint32_t*)&l01; lp.y = *(uint32_t*)&l23;
            *(uint2*)(sm + SM_WHH_HI + so) = hp;
            *(uint2*)(sm + SM_WHH_LO + so) = lp;
        }
        for (int u = tid; u < 2048; u += NTHR) {
            int row = u >> 6, k4 = u & 63;
            float4 v = *(const float4*)(Wih + (size_t)(n0 + row) * I_ + k4 * 4);
            __nv_bfloat162 h01 = __floats2bfloat162_rn(v.x, v.y);
            __nv_bfloat162 h23 = __floats2bfloat162_rn(v.z, v.w);
            __nv_bfloat162 l01 = __floats2bfloat162_rn(
                v.x - __bfloat162float(h01.x), v.y - __bfloat162float(h01.y));
            __nv_bfloat162 l23 = __floats2bfloat162_rn(
                v.z - __bfloat162float(h23.x), v.w - __bfloat162float(h23.y));
            int so = row * 512 + ((k4 * 8) ^ ((row & 7) * 16));
            uint2 hp; hp.x = *(uint32_t*)&h01; hp.y = *(uint32_t*)&h23;
            uint2 lp; lp.x = *(uint32_t*)&l01; lp.y = *(uint32_t*)&l23;
            *(uint2*)(sm + SM_WIH_HI + so) = hp;
            *(uint2*)(sm + SM_WIH_LO + so) = lp;
        }
        if (tid < 32)
            ((float*)(sm + SM_BIAS))[tid] = b_ih[n0 + tid] + b_hh[n0 + tid];
    }

    unsigned phase = 0;
    if (tid == 0) phase = ((volatile unsigned*)&g_bar_phase4[ctaM * 32])[0];
    __syncthreads();

    // Per-lane fragment address constants (proven in R7/R10)
    const int arow = (lid & 7) + ((lid >> 3) & 1) * 8;
    const int aka2 = ((lid >> 4) & 1) * 16;
    const int axor = (arow & 7) * 16;
    const uint32_t stage_base = smb + SM_ASTAGE + (uint32_t)stream * 32768;
    const uint32_t a_lane = stage_base + (uint32_t)(wm * 16 + arow) * 256;

    const int brow = wn * 16 + (lid & 7) + ((lid >> 4) & 1) * 8;
    const int bka2 = ((lid >> 3) & 1) * 16;
    const int bxor = (brow & 7) * 16;
    const uint32_t bhh_lane = smb + SM_WHH_HI + (uint32_t)brow * 2048;
    const uint32_t bih_lane = smb + SM_WIH_HI + (uint32_t)brow * 512;

    const int g  = lid >> 2;
    const int tg = lid & 3;
    const int xkb0 = stream * 256;   // x chunk's byte offset within W_ih rows

    // Pre-load x(t=0) into stage 0 (stage(t=0, j=0) = (0+0)&1 = 0)
    load_chunk(stage_base, 8 + stream, (const char*)g_h_hi[0],
               (const char*)g_h_lo[0], m0, 0, stid);
    asm volatile("cp.async.commit_group;");

    for (int t = 0; t < T_; t++) {
        const char* hhi = (const char*)g_h_hi[t & 1];
        const char* hlo = (const char*)g_h_lo[t & 1];

        float acc[2][2][4];
        #pragma unroll
        for (int p = 0; p < 2; p++)
            #pragma unroll
            for (int n = 0; n < 2; n++)
                #pragma unroll
                for (int j = 0; j < 4; j++) acc[p][n][j] = 0.f;

        // iter j: compute chunk j from stage (t+j)&1;
        //   j=0 -> x chunk (pre-staged); j=1..4 -> h chunk c = 2(j-1)+stream.
        // Load next chunk into stage (t+j+1)&1 (freed: its last reader was
        //   chunk j-1, done before this iteration's stream_bar).
        #pragma unroll
        for (int j = 0; j < 5; j++) {
            asm volatile("cp.async.wait_group 0;");
            stream_bar(stream);
            if (j < 4) {
                load_chunk(stage_base + (uint32_t)((t + j + 1) & 1) * 16384,
                           2 * j + stream, hhi, hlo, m0, t, stid);
                asm volatile("cp.async.commit_group;");
            } else if (t + 1 < T_) {
                // Pre-stage x of NEXT step (independent of h -> crosses barrier)
                load_chunk(stage_base + (uint32_t)((t + 1) & 1) * 16384,
                           8 + stream, hhi, hlo, m0, t + 1, stid);
                asm volatile("cp.async.commit_group;");
            }

            const uint32_t a_base = a_lane + (uint32_t)((t + j) & 1) * 16384;
            uint32_t b_base, b_dlo;
            int kb0;
            if (j == 0) { b_base = bih_lane; b_dlo = 16384; kb0 = xkb0; }
            else { int c = 2 * (j - 1) + stream;
                   b_base = bhh_lane; b_dlo = 65536; kb0 = c * 256; }

            #pragma unroll
            for (int kk = 0; kk < 8; kk++) {
                uint32_t ahi[4], alo[4], bh[4], bl[4];
                uint32_t ao = (uint32_t)((kk * 32 + aka2) ^ axor);
                ldsm_x4(ahi, a_base + ao);
                ldsm_x4(alo, a_base + 8192 + ao);
                uint32_t bo = (uint32_t)((kb0 + kk * 32 + bka2) ^ bxor);
                ldsm_x4(bh, b_base + bo);          // NON-trans: [n][k] row-major
                ldsm_x4(bl, b_base + b_dlo + bo);

                float* C0 = acc[kk & 1][0];
                float* C1 = acc[kk & 1][1];
                mma16816(C0, ahi, bh[0], bh[1]);   // Ahi*Bhi
                mma16816(C1, ahi, bh[2], bh[3]);
                mma16816(C0, ahi, bl[0], bl[1]);   // Ahi*Blo
                mma16816(C1, ahi, bl[2], bl[3]);
                mma16816(C0, alo, bh[0], bh[1]);   // Alo*Bhi
                mma16816(C1, alo, bh[2], bh[3]);
            }
        }
        __syncthreads();   // BOTH streams done computing before red-area reuse

        // ---- Epilogue, nt-split: stream s finalizes n-subtile nt==s ----
        {
            float vs[2][4];
            #pragma unroll
            for (int nt = 0; nt < 2; nt++)
                #pragma unroll
                for (int j = 0; j < 4; j++)
                    vs[nt][j] = acc[0][nt][j] + acc[1][nt][j];

            // red aliases stream0's stage (t&1): chunk j=4 data, fully consumed
            float* red = (float*)(sm + SM_ASTAGE + (uint32_t)(t & 1) * 16384);

            {   // write partials of the OTHER stream's half
                const int nt = 1 - stream;
                int nloc = wn * 16 + nt * 8 + tg * 2;
                #pragma unroll
                for (int rp = 0; rp < 2; rp++) {
                    int mloc = wm * 16 + g + rp * 8;
                    red[mloc * 32 + nloc]     = vs[nt][rp * 2 + 0];
                    red[mloc * 32 + nloc + 1] = vs[nt][rp * 2 + 1];
                }
            }
            __syncthreads();
            {   // finalize own half: +partial +bias, tanh, split-bf16 store
                const int nt = stream;
                __nv_bfloat16* __restrict__ ohi = g_h_hi[(t + 1) & 1];
                __nv_bfloat16* __restrict__ olo = g_h_lo[(t + 1) & 1];
                const float* bias = (const float*)(sm + SM_BIAS);
                const bool last = (t == T_ - 1);
                int nloc = wn * 16 + nt * 8 + tg * 2;
                int ng = n0 + nloc;
                float b0v = bias[nloc], b1v = bias[nloc + 1];
                #pragma unroll
                for (int rp = 0; rp < 2; rp++) {
                    int mloc = wm * 16 + g + rp * 8;
                    int mg = m0 + mloc;
                    float v0 = tanhf(vs[nt][rp * 2 + 0] + red[mloc * 32 + nloc] + b0v);
                    float v1 = tanhf(vs[nt][rp * 2 + 1] + red[mloc * 32 + nloc + 1] + b1v);
                    __nv_bfloat16 h0 = __float2bfloat16(v0);
                    __nv_bfloat16 h1 = __float2bfloat16(v1);
                    __nv_bfloat16 l0 = __float2bfloat16(v0 - __bfloat162float(h0));
                    __nv_bfloat16 l1 = __float2bfloat16(v1 - __bfloat162float(h1));
                    size_t idx = (size_t)mg * H_ + ng;
                    *(uint32_t*)(ohi + idx) =
                        ((uint32_t)*(uint16_t*)&h1 << 16) | *(uint16_t*)&h0;
                    *(uint32_t*)(olo + idx) =
                        ((uint32_t)*(uint16_t*)&l1 << 16) | *(uint16_t*)&l0;
                    if (last) {
                        float2 f2v; f2v.x = v0; f2v.y = v1;
                        *(float2*)(g_h32 + idx) = f2v;
                    }
                }
            }
        }

        __threadfence();   // h stores visible GPU-wide before barrier release
        group_barrier(ctaM, &phase);
    }
}

// ---------------------------------------------------------------------------
// fc epilogue: one block per batch; warp-per-output-column, lanes split K.
// ---------------------------------------------------------------------------
__global__ __launch_bounds__(256) void fc_kernel(
    const float* __restrict__ W_fc, const float* __restrict__ b_fc,
    float* __restrict__ out)
{
    __shared__ float4 hsv4[H_ / 4];
    const int b = blockIdx.x;
    const int tid = threadIdx.x;
    const int wid = tid >> 5;
    const int lid = tid & 31;

    hsv4[tid] = ((const float4*)(g_h32 + (size_t)b * H_))[tid];
    __syncthreads();

    #pragma unroll 4
    for (int oi = 0; oi < 32; oi++) {
        const int o = wid * 32 + oi;
        const float4* __restrict__ w4 = (const float4*)(W_fc + (size_t)o * H_);
        float a0 = 0.f, a1 = 0.f;
        #pragma unroll
        for (int i = 0; i < 8; i++) {
            float4 w = w4[lid + i * 32];
            float4 h = hsv4[lid + i * 32];
            if (i & 1) a1 += w.x * h.x + w.y * h.y + w.z * h.z + w.w * h.w;
            else       a0 += w.x * h.x + w.y * h.y + w.z * h.z + w.w * h.w;
        }
        float acc = a0 + a1;
        #pragma unroll
        for (int off = 16; off > 0; off >>= 1)
            acc += __shfl_xor_sync(0xFFFFFFFFu, acc, off);
        if (lid == 0) out[(size_t)b * O_ + o] = acc + b_fc[o];
    }
}

__global__ void copy_hidden(float* __restrict__ dst)
{
    int idx = blockIdx.x * blockDim.x + threadIdx.x;
    if (idx < B_ * H_) dst[idx] = g_h32[idx];
}

// ---------------------------------------------------------------------------
extern "C" void kernel_launch(void* const* d_in, const int* in_sizes, int n_in,
                              void* d_out, int out_size)
{
    const float* x      = (const float*)d_in[0];
    const float* hidden = (const float*)d_in[1];
    const float* W_ih   = (const float*)d_in[2];
    const float* W_hh   = (const float*)d_in[3];
    const float* b_ih   = (const float*)d_in[4];
    const float* b_hh   = (const float*)d_in[5];
    const float* W_fc   = (const float*)d_in[6];
    const float* b_fc   = (const float*)d_in[7];
    float* out = (float*)d_out;

    cudaFuncSetAttribute(rnn_persistent, cudaFuncAttributeMaxDynamicSharedMemorySize,
                         SM_TOTAL);

    static __nv_bfloat16 *p_xhi = nullptr, *p_xlo = nullptr,
                         *p_hhi = nullptr, *p_hlo = nullptr;
    if (!p_xhi) {
        cudaGetSymbolAddress((void**)&p_xhi, g_x_hi);
        cudaGetSymbolAddress((void**)&p_xlo, g_x_lo);
        cudaGetSymbolAddress((void**)&p_hhi, g_h_hi);
        cudaGetSymbolAddress((void**)&p_hlo, g_h_lo);
    }

    // 1) split x and initial hidden to bf16 hi/lo (W splits live in prologue)
    split_pair<<<(B_ * T_ * I_ + 255) / 256, 256>>>(x, p_xhi, p_xlo, B_ * T_ * I_);
    split_pair<<<(B_ * H_ + 255) / 256, 256>>>(hidden, p_hhi, p_hlo, B_ * H_);

    // 2) full recurrence in ONE persistent launch
    rnn_persistent<<<NB, NTHR, SM_TOTAL>>>(b_ih, b_hh, W_hh, W_ih);

    // 3) fc epilogue + hidden output
    fc_kernel<<<B_, 256>>>(W_fc, b_fc, out);
    if (out_size >= B_ * O_ + B_ * H_)
        copy_hidden<<<(B_ * H_ + 255) / 256, 256>>>(out + B_ * O_);
}